// round 4
// baseline (speedup 1.0000x reference)
#include <cuda_runtime.h>
#include <math.h>

#define SLEN 4096
#define EDIM 256
#define HDIM 256
#define TAGS 32
#define NEGV (-10000.0f)
#define NBLK 32        // LSTM blocks per direction
#define STARTTAG 30
#define STOPTAG  31

// ---------------- scratch (device globals; no allocation allowed) ----------------
__device__ float g_xg[2][SLEN][4 * HDIM];          // 32 MB : precomputed input gates
__device__ __align__(16) float g_hs[2][SLEN][HDIM];// 8 MB  : hidden states (scan order)
__device__ float g_feats[SLEN][TAGS];              // 512 KB
__device__ int   g_cnt[2][SLEN];                   // per-step arrival counters

__device__ __forceinline__ float sigmoidf_(float x) { return 1.0f / (1.0f + expf(-x)); }

// ---------------- K1: xg[d][t][r] = emb[sent_d(t)] . w_ih_d[r] + b_d[r] ----------
__global__ void k1_xg(const int* __restrict__ sent,
                      const float* __restrict__ embedding,
                      const float* __restrict__ w_ih_f, const float* __restrict__ b_f,
                      const float* __restrict__ w_ih_b, const float* __restrict__ b_b)
{
    __shared__ __align__(16) float embs[16][EDIM];
    const int d  = blockIdx.z;
    const int t0 = blockIdx.x * 16;
    const int n  = blockIdx.y * 256 + threadIdx.x;   // gate row 0..1023

    for (int tt = 0; tt < 16; tt++) {
        int pos  = t0 + tt;
        int spos = d ? (SLEN - 1 - pos) : pos;
        int tok  = sent[spos];
        embs[tt][threadIdx.x] = embedding[(size_t)tok * EDIM + threadIdx.x];
    }
    __syncthreads();

    const float* W = d ? w_ih_b : w_ih_f;
    const float* B = d ? b_b    : b_f;
    float acc[16];
    float bias = B[n];
#pragma unroll
    for (int tt = 0; tt < 16; tt++) acc[tt] = bias;

    const float4* Wr = (const float4*)(W + (size_t)n * EDIM);
#pragma unroll 4
    for (int e4 = 0; e4 < EDIM / 4; e4++) {
        float4 w4 = __ldg(&Wr[e4]);
#pragma unroll
        for (int tt = 0; tt < 16; tt++) {
            float4 ev = *(const float4*)&embs[tt][e4 * 4];
            float a = acc[tt];
            a = fmaf(w4.x, ev.x, a);
            a = fmaf(w4.y, ev.y, a);
            a = fmaf(w4.z, ev.z, a);
            a = fmaf(w4.w, ev.w, a);
            acc[tt] = a;
        }
    }
#pragma unroll
    for (int tt = 0; tt < 16; tt++) g_xg[d][t0 + tt][n] = acc[tt];
}

// ---------------- K2: persistent bidirectional LSTM recurrence -------------------
// 2 dirs x 32 blocks x 256 threads. Warp wi owns h-index j = blk*8 + wi.
// Lane (r,g): gate row r (of j's 4 gates), cols [g*32, g*32+32). 32 weights/lane.
// Handshake: stcg h into g_hs -> syncthreads -> red.release.gpu (thread 0);
// reader: ld.acquire.gpu poll (thread 0) -> syncthreads -> __ldcg h (L1-bypass).
__global__ void __launch_bounds__(256, 1) k2_lstm(
    const float* __restrict__ h0, const float* __restrict__ c0,
    const float* __restrict__ w_hh_f, const float* __restrict__ w_hh_b)
{
    const int d    = blockIdx.x >> 5;
    const int blk  = blockIdx.x & 31;
    const int wi   = threadIdx.x >> 5;   // 0..7
    const int lane = threadIdx.x & 31;
    const int j    = blk * 8 + wi;       // 0..255
    const int r    = lane >> 3;          // gate row 0..3
    const int g    = lane & 7;           // col group 0..7

    const float* W = d ? w_hh_b : w_hh_f;
    float4 w4[8];
    const float4* wp = (const float4*)(W + ((size_t)(r * HDIM + j)) * HDIM + g * 32);
#pragma unroll
    for (int k = 0; k < 8; k++) w4[k] = __ldg(&wp[k]);

    float cst = 0.0f;
    if (lane == 0) cst = c0[d * HDIM + j];

    int* cnt = &g_cnt[d][0];

    for (int t = 0; t < SLEN; t++) {
        // prefetch xg for this step (independent of the barrier)
        float xgv = 0.0f;
        if (g == 0) xgv = __ldg(&g_xg[d][t][r * HDIM + j]);

        if (t > 0) {
            if (threadIdx.x == 0) {
                unsigned v;
                do {
                    asm volatile("ld.acquire.gpu.u32 %0, [%1];"
                                 : "=r"(v) : "l"(cnt + (t - 1)) : "memory");
                } while (v != (unsigned)NBLK);
            }
            __syncthreads();
        }

        const float4* hp = (t == 0) ? (const float4*)(h0 + d * HDIM)
                                    : (const float4*)g_hs[d][t - 1];
        hp += g * 8;                         // g*32 floats
        float4 h4[8];
#pragma unroll
        for (int k = 0; k < 8; k++) h4[k] = __ldcg(hp + k);

        float acc4[4] = {0.f, 0.f, 0.f, 0.f};
#pragma unroll
        for (int k = 0; k < 8; k++) {
            float a = acc4[k & 3];
            a = fmaf(w4[k].x, h4[k].x, a);
            a = fmaf(w4[k].y, h4[k].y, a);
            a = fmaf(w4[k].z, h4[k].z, a);
            a = fmaf(w4[k].w, h4[k].w, a);
            acc4[k & 3] = a;
        }
        float acc = (acc4[0] + acc4[1]) + (acc4[2] + acc4[3]);
        acc += __shfl_xor_sync(0xffffffffu, acc, 1);
        acc += __shfl_xor_sync(0xffffffffu, acc, 2);
        acc += __shfl_xor_sync(0xffffffffu, acc, 4);

        float val = 0.0f;
        if (g == 0) {
            float a = acc + xgv;             // gates: i(0) f(1) g(2) o(3) by r
            val = (r == 2) ? tanhf(a) : sigmoidf_(a);
        }
        float iv = __shfl_sync(0xffffffffu, val, 0);
        float fv = __shfl_sync(0xffffffffu, val, 8);
        float gv = __shfl_sync(0xffffffffu, val, 16);
        float ov = __shfl_sync(0xffffffffu, val, 24);

        if (lane == 0) {
            cst = fmaf(fv, cst, iv * gv);
            float hv = ov * tanhf(cst);
            __stcg(&g_hs[d][t][j], hv);
        }
        __syncthreads();
        if (threadIdx.x == 0) {
            asm volatile("red.release.gpu.add.u32 [%0], 1;"
                         :: "l"(cnt + t) : "memory");
        }
    }
}

// ---------------- K3: feats[t] = [hs_f[t], hs_b[S-1-t]] @ lin_w^T + lin_b --------
__global__ void k3_feats(const float* __restrict__ lin_w, const float* __restrict__ lin_b)
{
    __shared__ __align__(16) float cat[2 * HDIM];
    const int t   = blockIdx.x;
    const int tid = threadIdx.x;                // 256
    cat[tid]        = g_hs[0][t][tid];
    cat[HDIM + tid] = g_hs[1][SLEN - 1 - t][tid];
    __syncthreads();

    const int n = tid >> 3, seg = tid & 7;
    const float* w  = lin_w + (size_t)n * 2 * HDIM + seg * 64;
    const float* cc = cat + seg * 64;
    float s = 0.0f;
#pragma unroll 16
    for (int k = 0; k < 64; k++) s = fmaf(w[k], cc[k], s);
    s += __shfl_xor_sync(0xffffffffu, s, 1);
    s += __shfl_xor_sync(0xffffffffu, s, 2);
    s += __shfl_xor_sync(0xffffffffu, s, 4);
    if (seg == 0) g_feats[t][n] = s + lin_b[n];
}

// ---------------- K4: single-warp Viterbi + backtrack (bps in SMEM) --------------
// Lane n = next-tag. fv broadcast via shfl; in-lane 5-level first-max tree exactly
// reproduces jnp.argmax (first occurrence on ties). No block syncs at all.
__global__ void __launch_bounds__(32, 1) k4_viterbi(
    const float* __restrict__ trans, float* __restrict__ out, int out_size)
{
    extern __shared__ unsigned char bps[];      // SLEN*TAGS bytes = 128 KB
    const int lane = threadIdx.x;

    float trn[TAGS];
#pragma unroll
    for (int p = 0; p < TAGS; p++) trn[p] = __ldg(&trans[lane * TAGS + p]);
    const float stop_tr = __ldg(&trans[STOPTAG * TAGS + lane]);

    float fv  = (lane == STARTTAG) ? 0.0f : NEGV;
    float ftc = g_feats[0][lane];
    float ftn = g_feats[1][lane];

    for (int t = 0; t < SLEN; t++) {
        float v[TAGS];
        int   bi[TAGS];
#pragma unroll
        for (int p = 0; p < TAGS; p++) {
            v[p]  = __shfl_sync(0xffffffffu, fv, p) + trn[p];
            bi[p] = p;
        }
        // first-max tree: strict > keeps the lower index on ties
#pragma unroll
        for (int s = 1; s < TAGS; s <<= 1) {
#pragma unroll
            for (int k = 0; k < TAGS; k += 2 * s) {
                if (v[k + s] > v[k]) { v[k] = v[k + s]; bi[k] = bi[k + s]; }
            }
        }
        bps[t * TAGS + lane] = (unsigned char)bi[0];
        fv  = v[0] + ftc;
        ftc = ftn;
        ftn = (t + 2 < SLEN) ? g_feats[t + 2][lane] : 0.0f;
    }

    // final = fv + transitions[STOP]; argmax with first-occurrence tie-break
    float v = fv + stop_tr;
    int   b = lane;
#pragma unroll
    for (int ofs = 16; ofs > 0; ofs >>= 1) {
        float ov = __shfl_down_sync(0xffffffffu, v, ofs);
        int   oi = __shfl_down_sync(0xffffffffu, b, ofs);
        if (ov > v || (ov == v && oi < b)) { v = ov; b = oi; }
    }

    if (lane == 0) {
        const int off = (out_size > SLEN) ? 1 : 0;
        if (off) out[0] = v;
        int cur = b;
        for (int t = SLEN - 1; t >= 0; t--) {   // path[t]; then hop to t-1
            int idx = off + t;
            if (idx < out_size) out[idx] = (float)cur;
            cur = bps[t * TAGS + cur];
        }
    }
}

// ---------------- launch ----------------------------------------------------------
extern "C" void kernel_launch(void* const* d_in, const int* in_sizes, int n_in,
                              void* d_out, int out_size)
{
    (void)in_sizes; (void)n_in;
    const int*   sent      = (const int*)  d_in[0];
    const float* h0        = (const float*)d_in[1];
    const float* c0        = (const float*)d_in[2];
    const float* embedding = (const float*)d_in[3];
    const float* w_ih_f    = (const float*)d_in[4];
    const float* w_hh_f    = (const float*)d_in[5];
    const float* b_f       = (const float*)d_in[6];
    const float* w_ih_b    = (const float*)d_in[7];
    const float* w_hh_b    = (const float*)d_in[8];
    const float* b_b       = (const float*)d_in[9];
    const float* lin_w     = (const float*)d_in[10];
    const float* lin_b     = (const float*)d_in[11];
    const float* trans     = (const float*)d_in[12];

    // reset per-step barrier counters (captured into the graph, runs every replay)
    void* cntp = nullptr;
    cudaGetSymbolAddress(&cntp, g_cnt);
    cudaMemsetAsync(cntp, 0, sizeof(int) * 2 * SLEN, 0);

    dim3 g1(SLEN / 16, 4, 2);
    k1_xg<<<g1, 256>>>(sent, embedding, w_ih_f, b_f, w_ih_b, b_b);
    k2_lstm<<<2 * NBLK, 256>>>(h0, c0, w_hh_f, w_hh_b);
    k3_feats<<<SLEN, 256>>>(lin_w, lin_b);

    cudaFuncSetAttribute(k4_viterbi, cudaFuncAttributeMaxDynamicSharedMemorySize,
                         SLEN * TAGS);
    k4_viterbi<<<1, 32, SLEN * TAGS>>>(trans, (float*)d_out, out_size);
}

// round 5
// speedup vs baseline: 2.0270x; 2.0270x over previous
#include <cuda_runtime.h>
#include <math.h>

#define SLEN 4096
#define EDIM 256
#define HDIM 256
#define TAGS 32
#define NEGV (-10000.0f)
#define CL 8            // CTAs per cluster (one cluster per direction)
#define STARTTAG 30
#define STOPTAG  31

// ---------------- scratch (device globals; no allocation allowed) ----------------
__device__ float g_xg[2][SLEN][4 * HDIM];           // 32 MB : precomputed input gates
__device__ __align__(16) float g_hs[2][SLEN][HDIM]; // 8 MB  : hidden states
__device__ float g_feats[SLEN][TAGS];               // 512 KB

// packed fp32x2 FMA (Blackwell FFMA2): d = a*b + c elementwise on float2
__device__ __forceinline__ float2 ffma2(float2 a, float2 b, float2 c) {
    float2 d;
    asm("fma.rn.f32x2 %0, %1, %2, %3;"
        : "=l"(*reinterpret_cast<unsigned long long*>(&d))
        : "l"(*reinterpret_cast<unsigned long long*>(&a)),
          "l"(*reinterpret_cast<unsigned long long*>(&b)),
          "l"(*reinterpret_cast<unsigned long long*>(&c)));
    return d;
}

// ---------------- K1: xg[d][t][r] = emb[sent_d(t)] . w_ih_d[r] + b_d[r] ----------
__global__ void k1_xg(const int* __restrict__ sent,
                      const float* __restrict__ embedding,
                      const float* __restrict__ w_ih_f, const float* __restrict__ b_f,
                      const float* __restrict__ w_ih_b, const float* __restrict__ b_b)
{
    __shared__ __align__(16) float embs[16][EDIM];
    const int d  = blockIdx.z;
    const int t0 = blockIdx.x * 16;
    const int n  = blockIdx.y * 256 + threadIdx.x;   // gate row 0..1023

    for (int tt = 0; tt < 16; tt++) {
        int pos  = t0 + tt;
        int spos = d ? (SLEN - 1 - pos) : pos;
        int tok  = sent[spos];
        embs[tt][threadIdx.x] = embedding[(size_t)tok * EDIM + threadIdx.x];
    }
    __syncthreads();

    const float* W = d ? w_ih_b : w_ih_f;
    const float* B = d ? b_b    : b_f;
    float2 acc[16];
    float bias = B[n];
#pragma unroll
    for (int tt = 0; tt < 16; tt++) acc[tt] = make_float2(bias, 0.0f);

    const float4* Wr = (const float4*)(W + (size_t)n * EDIM);
#pragma unroll 4
    for (int e4 = 0; e4 < EDIM / 4; e4++) {
        float4 w4 = __ldg(&Wr[e4]);
        float2 wA = make_float2(w4.x, w4.y);
        float2 wB = make_float2(w4.z, w4.w);
#pragma unroll
        for (int tt = 0; tt < 16; tt++) {
            float4 ev = *(const float4*)&embs[tt][e4 * 4];
            acc[tt] = ffma2(wA, make_float2(ev.x, ev.y), acc[tt]);
            acc[tt] = ffma2(wB, make_float2(ev.z, ev.w), acc[tt]);
        }
    }
#pragma unroll
    for (int tt = 0; tt < 16; tt++) g_xg[d][t0 + tt][n] = acc[tt].x + acc[tt].y;
}

// ---------------- K2: clustered bidirectional LSTM recurrence --------------------
// Grid = 16 CTAs = 2 clusters of 8 (one cluster per direction), 512 thr/CTA.
// CTA (rank) owns h-indices j in [rank*32, rank*32+32) -> 128 gate rows.
// Thread map: warp w covers jl in {2w, 2w+1}; lane = r8*4+q, r8=(jsub*4+gate),
// q = col quarter. Thread holds 64 W_hh weights (cols {c: c=4*(m*4+q)..+3})
// chunk-interleaved so LDS of h is bank-conflict-free.
// Exchange: producers DSMEM-broadcast their h slice to all 8 CTAs' SMEM;
// per-CTA monotonic step flags, st.release.cluster / LDS-acquire poll.
__global__ void __launch_bounds__(512, 1) __cluster_dims__(CL, 1, 1)
k2_lstm(const float* __restrict__ h0, const float* __restrict__ c0,
        const float* __restrict__ w_hh_f, const float* __restrict__ w_hh_b)
{
    __shared__ __align__(16) float hbuf[2][HDIM];   // full h, assembled via DSMEM
    __shared__ unsigned flags[CL];                  // flags[c] = steps CTA c completed

    const int d = blockIdx.x >> 3;                  // cluster id = direction
    unsigned crank;
    asm("mov.u32 %0, %%cluster_ctarank;" : "=r"(crank));
    const int tid  = threadIdx.x;
    const int w    = tid >> 5;
    const int lane = tid & 31;
    const int q    = lane & 3;                      // column quarter
    const int r8   = lane >> 2;                     // 0..7
    const int gate = r8 & 3;                        // i,f,g,o
    const int jl   = w * 2 + (r8 >> 2);             // 0..31
    const int j    = (int)crank * 32 + jl;          // global h index 0..255
    const int grow = gate * HDIM + j;               // gate-row in [0,1024)

    // weights: 16 float4 chunks, chunk c = m*4+q covers cols [4c, 4c+4)
    const float* W = d ? w_hh_b : w_hh_f;
    float4 wr[16];
#pragma unroll
    for (int m = 0; m < 16; m++)
        wr[m] = *(const float4*)(W + (size_t)grow * HDIM + (size_t)(m * 4 + q) * 4);

    // precompute DSMEM addresses of every cluster CTA's hbuf / flags
    unsigned hb_u32 = (unsigned)__cvta_generic_to_shared(&hbuf[0][0]);
    unsigned fl_u32 = (unsigned)__cvta_generic_to_shared(&flags[0]);
    unsigned rh[CL], rf[CL];
#pragma unroll
    for (int c = 0; c < CL; c++) {
        asm("mapa.shared::cluster.u32 %0, %1, %2;" : "=r"(rh[c]) : "r"(hb_u32), "r"(c));
        asm("mapa.shared::cluster.u32 %0, %1, %2;" : "=r"(rf[c]) : "r"(fl_u32), "r"(c));
    }

    if (tid < CL)   flags[tid]    = 0u;
    if (tid < HDIM) hbuf[1][tid]  = h0[d * HDIM + tid];  // H_0 parity: (s-1)&1 at s=1
    __syncthreads();
    // all CTAs' flags/hbuf initialized before any cross-CTA traffic
    asm volatile("barrier.cluster.arrive.aligned;" ::: "memory");
    asm volatile("barrier.cluster.wait.aligned;"   ::: "memory");

    const bool prod = (lane == 0) || (lane == 16); // holds result for its j
    float cst = prod ? c0[d * HDIM + j] : 0.0f;
    const unsigned myflag = fl_u32 + (unsigned)(lane & 7) * 4u;

    for (int s = 1; s <= SLEN; s++) {
        const int t = s - 1;
        // xg prefetch (independent of flags) — hides DRAM latency behind the poll
        float xw = 0.0f;
        if (q == 0) xw = __ldg(&g_xg[d][t][grow]);

        if (s > 1) {                                // wait: all CTAs completed s-1
            bool ok;
            do {
                unsigned fv_ = 0xffffffffu;
                if (lane < CL)
                    asm volatile("ld.acquire.cluster.shared::cta.u32 %0, [%1];"
                                 : "=r"(fv_) : "r"(myflag) : "memory");
                ok = __all_sync(0xffffffffu, fv_ >= (unsigned)(s - 1));
            } while (!ok);
        }

        const float* hsm = &hbuf[(s - 1) & 1][0];
        float2 acc[4];
#pragma unroll
        for (int k = 0; k < 4; k++) acc[k] = make_float2(0.0f, 0.0f);
#pragma unroll
        for (int m = 0; m < 16; m++) {
            float4 h4 = *(const float4*)(hsm + (m * 4 + q) * 4);
            float4 w4 = wr[m];
            float2 a  = acc[m & 3];
            a = ffma2(make_float2(w4.x, w4.y), make_float2(h4.x, h4.y), a);
            a = ffma2(make_float2(w4.z, w4.w), make_float2(h4.z, h4.w), a);
            acc[m & 3] = a;
        }
        float accS = ((acc[0].x + acc[0].y) + (acc[1].x + acc[1].y))
                   + ((acc[2].x + acc[2].y) + (acc[3].x + acc[3].y));
        accS += __shfl_xor_sync(0xffffffffu, accS, 1);
        accS += __shfl_xor_sync(0xffffffffu, accS, 2);

        // activations on the q==0 lanes (gate from r8); others compute garbage
        float av  = accS + xw;
        float val = (gate == 2) ? tanhf(av) : 1.0f / (1.0f + expf(-av));

        float iv = __shfl_sync(0xffffffffu, val, (lane & 16) + 0);
        float fv = __shfl_sync(0xffffffffu, val, (lane & 16) + 4);
        float gv = __shfl_sync(0xffffffffu, val, (lane & 16) + 8);
        float ov = __shfl_sync(0xffffffffu, val, (lane & 16) + 12);

        if (prod) {
            cst = fmaf(fv, cst, iv * gv);
            float hv = ov * tanhf(cst);
            unsigned off = (unsigned)((s & 1) * HDIM + j) * 4u;
#pragma unroll
            for (int c = 0; c < CL; c++)                 // broadcast slice to cluster
                asm volatile("st.shared::cluster.f32 [%0], %1;"
                             :: "r"(rh[c] + off), "f"(hv) : "memory");
            __stcg(&g_hs[d][t][j], hv);
        }
        __syncthreads();                                 // whole CTA done with H_{s-1}
        if (tid < CL)                                    // release: stores before flag
            asm volatile("st.release.cluster.shared::cluster.u32 [%0], %1;"
                         :: "r"(rf[tid] + crank * 4u), "r"((unsigned)s) : "memory");
    }

    // no CTA may exit while peers still write into its SMEM
    asm volatile("barrier.cluster.arrive.aligned;" ::: "memory");
    asm volatile("barrier.cluster.wait.aligned;"   ::: "memory");
}

// ---------------- K3: feats[t] = [hs_f[t], hs_b[S-1-t]] @ lin_w^T + lin_b --------
__global__ void k3_feats(const float* __restrict__ lin_w, const float* __restrict__ lin_b)
{
    __shared__ __align__(16) float cat[2 * HDIM];
    const int t   = blockIdx.x;
    const int tid = threadIdx.x;                // 256
    cat[tid]        = g_hs[0][t][tid];
    cat[HDIM + tid] = g_hs[1][SLEN - 1 - t][tid];
    __syncthreads();

    const int n = tid >> 3, seg = tid & 7;
    const float* w  = lin_w + (size_t)n * 2 * HDIM + seg * 64;
    const float* cc = cat + seg * 64;
    float s = 0.0f;
#pragma unroll 16
    for (int k = 0; k < 64; k++) s = fmaf(w[k], cc[k], s);
    s += __shfl_xor_sync(0xffffffffu, s, 1);
    s += __shfl_xor_sync(0xffffffffu, s, 2);
    s += __shfl_xor_sync(0xffffffffu, s, 4);
    if (seg == 0) g_feats[t][n] = s + lin_b[n];
}

// ---------------- K4: single-warp Viterbi + backtrack (bps in SMEM) --------------
__global__ void __launch_bounds__(32, 1) k4_viterbi(
    const float* __restrict__ trans, float* __restrict__ out, int out_size)
{
    extern __shared__ unsigned char bps[];      // SLEN*TAGS bytes = 128 KB
    const int lane = threadIdx.x;

    float trn[TAGS];
#pragma unroll
    for (int p = 0; p < TAGS; p++) trn[p] = __ldg(&trans[lane * TAGS + p]);
    const float stop_tr = __ldg(&trans[STOPTAG * TAGS + lane]);

    float fv  = (lane == STARTTAG) ? 0.0f : NEGV;
    float ftc = g_feats[0][lane];
    float ftn = g_feats[1][lane];

    for (int t = 0; t < SLEN; t++) {
        float v[TAGS];
        int   bi[TAGS];
#pragma unroll
        for (int p = 0; p < TAGS; p++) {
            v[p]  = __shfl_sync(0xffffffffu, fv, p) + trn[p];
            bi[p] = p;
        }
        // first-max tree: strict > keeps the lower index on ties (== jnp.argmax)
#pragma unroll
        for (int s = 1; s < TAGS; s <<= 1) {
#pragma unroll
            for (int k = 0; k < TAGS; k += 2 * s) {
                if (v[k + s] > v[k]) { v[k] = v[k + s]; bi[k] = bi[k + s]; }
            }
        }
        bps[t * TAGS + lane] = (unsigned char)bi[0];
        fv  = v[0] + ftc;
        ftc = ftn;
        ftn = (t + 2 < SLEN) ? g_feats[t + 2][lane] : 0.0f;
    }

    float v = fv + stop_tr;
    int   b = lane;
#pragma unroll
    for (int ofs = 16; ofs > 0; ofs >>= 1) {
        float ov = __shfl_down_sync(0xffffffffu, v, ofs);
        int   oi = __shfl_down_sync(0xffffffffu, b, ofs);
        if (ov > v || (ov == v && oi < b)) { v = ov; b = oi; }
    }

    if (lane == 0) {
        const int off = (out_size > SLEN) ? 1 : 0;
        if (off) out[0] = v;
        int cur = b;
        for (int t = SLEN - 1; t >= 0; t--) {
            int idx = off + t;
            if (idx < out_size) out[idx] = (float)cur;
            cur = bps[t * TAGS + cur];
        }
    }
}

// ---------------- launch ----------------------------------------------------------
extern "C" void kernel_launch(void* const* d_in, const int* in_sizes, int n_in,
                              void* d_out, int out_size)
{
    (void)in_sizes; (void)n_in;
    const int*   sent      = (const int*)  d_in[0];
    const float* h0        = (const float*)d_in[1];
    const float* c0        = (const float*)d_in[2];
    const float* embedding = (const float*)d_in[3];
    const float* w_ih_f    = (const float*)d_in[4];
    const float* w_hh_f    = (const float*)d_in[5];
    const float* b_f       = (const float*)d_in[6];
    const float* w_ih_b    = (const float*)d_in[7];
    const float* w_hh_b    = (const float*)d_in[8];
    const float* b_b       = (const float*)d_in[9];
    const float* lin_w     = (const float*)d_in[10];
    const float* lin_b     = (const float*)d_in[11];
    const float* trans     = (const float*)d_in[12];

    dim3 g1(SLEN / 16, 4, 2);
    k1_xg<<<g1, 256>>>(sent, embedding, w_ih_f, b_f, w_ih_b, b_b);
    k2_lstm<<<2 * CL, 512>>>(h0, c0, w_hh_f, w_hh_b);
    k3_feats<<<SLEN, 256>>>(lin_w, lin_b);

    cudaFuncSetAttribute(k4_viterbi, cudaFuncAttributeMaxDynamicSharedMemorySize,
                         SLEN * TAGS);
    k4_viterbi<<<1, 32, SLEN * TAGS>>>(trans, (float*)d_out, out_size);
}

// round 6
// speedup vs baseline: 2.5617x; 1.2638x over previous
#include <cuda_runtime.h>
#include <math.h>

#define SLEN 4096
#define EDIM 256
#define HDIM 256
#define TAGS 32
#define NEGV (-10000.0f)
#define CL 8            // CTAs per cluster (one cluster per direction)
#define STARTTAG 30
#define STOPTAG  31

// ---------------- scratch (device globals; no allocation allowed) ----------------
__device__ float g_xg[2][SLEN][4 * HDIM];           // 32 MB : precomputed input gates
__device__ __align__(16) float g_hs[2][SLEN][HDIM]; // 8 MB  : hidden states
__device__ float g_feats[SLEN][TAGS];               // 512 KB

// packed fp32x2 FMA (Blackwell FFMA2): d = a*b + c elementwise on float2
__device__ __forceinline__ float2 ffma2(float2 a, float2 b, float2 c) {
    float2 d;
    asm("fma.rn.f32x2 %0, %1, %2, %3;"
        : "=l"(*reinterpret_cast<unsigned long long*>(&d))
        : "l"(*reinterpret_cast<unsigned long long*>(&a)),
          "l"(*reinterpret_cast<unsigned long long*>(&b)),
          "l"(*reinterpret_cast<unsigned long long*>(&c)));
    return d;
}

// fast sigmoid/tanh via MUFU (__expf rel err ~1e-7: safe for argmax margins)
__device__ __forceinline__ float fast_sigmoid(float x) {
    float e = __expf(-x);
    return __fdividef(1.0f, 1.0f + e);
}
__device__ __forceinline__ float fast_tanh(float x) {
    float e = __expf(-2.0f * x);
    return __fdividef(1.0f - e, 1.0f + e);
}

// ---------------- K1: xg[d][t][r] = emb[sent_d(t)] . w_ih_d[r] + b_d[r] ----------
__global__ void k1_xg(const int* __restrict__ sent,
                      const float* __restrict__ embedding,
                      const float* __restrict__ w_ih_f, const float* __restrict__ b_f,
                      const float* __restrict__ w_ih_b, const float* __restrict__ b_b)
{
    __shared__ __align__(16) float embs[16][EDIM];
    const int d  = blockIdx.z;
    const int t0 = blockIdx.x * 16;
    const int n  = blockIdx.y * 256 + threadIdx.x;   // gate row 0..1023

    for (int tt = 0; tt < 16; tt++) {
        int pos  = t0 + tt;
        int spos = d ? (SLEN - 1 - pos) : pos;
        int tok  = sent[spos];
        embs[tt][threadIdx.x] = embedding[(size_t)tok * EDIM + threadIdx.x];
    }
    __syncthreads();

    const float* W = d ? w_ih_b : w_ih_f;
    const float* B = d ? b_b    : b_f;
    float2 acc[16];
    float bias = B[n];
#pragma unroll
    for (int tt = 0; tt < 16; tt++) acc[tt] = make_float2(bias, 0.0f);

    const float4* Wr = (const float4*)(W + (size_t)n * EDIM);
#pragma unroll 4
    for (int e4 = 0; e4 < EDIM / 4; e4++) {
        float4 w4 = __ldg(&Wr[e4]);
        float2 wA = make_float2(w4.x, w4.y);
        float2 wB = make_float2(w4.z, w4.w);
#pragma unroll
        for (int tt = 0; tt < 16; tt++) {
            float4 ev = *(const float4*)&embs[tt][e4 * 4];
            acc[tt] = ffma2(wA, make_float2(ev.x, ev.y), acc[tt]);
            acc[tt] = ffma2(wB, make_float2(ev.z, ev.w), acc[tt]);
        }
    }
#pragma unroll
    for (int tt = 0; tt < 16; tt++) g_xg[d][t0 + tt][n] = acc[tt].x + acc[tt].y;
}

// ---------------- K2: clustered bidirectional LSTM recurrence --------------------
// Grid = 16 CTAs = 2 clusters of 8 (one per direction), 256 thr/CTA.
// CTA rank owns j in [rank*32, rank*32+32). Warp w owns jl in [4w, 4w+4).
// Lane l: a=l>>3 -> jl=4w+a; gate=(l>>1)&3; half=l&1. Thread holds 128 W_hh
// weights: row (gate*H + j), col chunks c=m*2+half (cols 4c..4c+3), m=0..31.
// Handshake: producers DSMEM-store h slice to all 8 CTAs; __syncthreads;
// tid0: fence.acq_rel.cluster + 8 remote mbarrier.arrive. Consumers:
// mbarrier.try_wait.parity.acquire.cluster (HW sleep -> no spin pressure).
__global__ void __launch_bounds__(256, 1) __cluster_dims__(CL, 1, 1)
k2_lstm(const float* __restrict__ h0, const float* __restrict__ c0,
        const float* __restrict__ w_hh_f, const float* __restrict__ w_hh_b)
{
    __shared__ __align__(16) float hbuf[2][HDIM];   // full h, assembled via DSMEM
    __shared__ __align__(8) unsigned long long mbar;

    const int d = blockIdx.x >> 3;                  // cluster id = direction
    unsigned crank;
    asm("mov.u32 %0, %%cluster_ctarank;" : "=r"(crank));
    const int tid  = threadIdx.x;
    const int w    = tid >> 5;
    const int l    = tid & 31;
    const int a    = l >> 3;                        // j slot within warp
    const int gate = (l >> 1) & 3;                  // i,f,g,o
    const int half = l & 1;                         // column half (interleaved)
    const int jl   = w * 4 + a;                     // 0..31
    const int j    = (int)crank * 32 + jl;          // global h index
    const int grow = gate * HDIM + j;               // gate row in [0,1024)

    const float* W = d ? w_hh_b : w_hh_f;
    float4 wr[32];                                  // 128 weights / thread
#pragma unroll
    for (int m = 0; m < 32; m++)
        wr[m] = *(const float4*)(W + (size_t)grow * HDIM + (size_t)(m * 2 + half) * 4);

    unsigned hb = (unsigned)__cvta_generic_to_shared(&hbuf[0][0]);
    unsigned mb = (unsigned)__cvta_generic_to_shared(&mbar);
    unsigned rh[CL], rm[CL];
#pragma unroll
    for (int c = 0; c < CL; c++) {
        asm("mapa.shared::cluster.u32 %0, %1, %2;" : "=r"(rh[c]) : "r"(hb), "r"(c));
        asm("mapa.shared::cluster.u32 %0, %1, %2;" : "=r"(rm[c]) : "r"(mb), "r"(c));
    }

    if (tid == 0)
        asm volatile("mbarrier.init.shared.b64 [%0], %1;" :: "r"(mb), "r"(CL) : "memory");
    hbuf[0][tid] = h0[d * HDIM + tid];              // step 1 reads hbuf[0]  (h0!)
    __syncthreads();
    asm volatile("barrier.cluster.arrive.aligned;" ::: "memory");
    asm volatile("barrier.cluster.wait.aligned;"   ::: "memory");

    const bool prod = ((l & 7) == 0);               // one lane per (warp, j)
    float cst = prod ? c0[d * HDIM + j] : 0.0f;

    for (int s = 1; s <= SLEN; s++) {
        const int t = s - 1;
        // xg prefetch: issued before the wait, overlaps the mbarrier sleep
        float xw = __ldg(&g_xg[d][t][grow]);

        if (s > 1) {                                // wait completion of step s-1
            unsigned par = (unsigned)(s & 1);
            unsigned done;
            asm volatile(
                "{\n\t.reg .pred p;\n\t"
                "mbarrier.try_wait.parity.acquire.cluster.shared::cta.b64 p, [%1], %2, 0x989680;\n\t"
                "selp.b32 %0, 1, 0, p;\n\t}"
                : "=r"(done) : "r"(mb), "r"(par) : "memory");
            while (!done) {
                asm volatile(
                    "{\n\t.reg .pred p;\n\t"
                    "mbarrier.try_wait.parity.acquire.cluster.shared::cta.b64 p, [%1], %2, 0x989680;\n\t"
                    "selp.b32 %0, 1, 0, p;\n\t}"
                    : "=r"(done) : "r"(mb), "r"(par) : "memory");
            }
        }

        const float* hsm = &hbuf[(s - 1) & 1][0];
        float2 acc[4];
#pragma unroll
        for (int k = 0; k < 4; k++) acc[k] = make_float2(0.0f, 0.0f);
#pragma unroll
        for (int m = 0; m < 32; m++) {
            float4 h4 = *(const float4*)(hsm + (m * 2 + half) * 4);
            float4 w4 = wr[m];
            float2 ac = acc[m & 3];
            ac = ffma2(make_float2(w4.x, w4.y), make_float2(h4.x, h4.y), ac);
            ac = ffma2(make_float2(w4.z, w4.w), make_float2(h4.z, h4.w), ac);
            acc[m & 3] = ac;
        }
        float accS = ((acc[0].x + acc[0].y) + (acc[1].x + acc[1].y))
                   + ((acc[2].x + acc[2].y) + (acc[3].x + acc[3].y));
        accS += __shfl_xor_sync(0xffffffffu, accS, 1);   // combine halves

        float av  = accS + xw;
        float val = (gate == 2) ? fast_tanh(av) : fast_sigmoid(av);

        const int base = l & 24;                    // lane group of this j
        float iv = __shfl_sync(0xffffffffu, val, base + 0);
        float fv = __shfl_sync(0xffffffffu, val, base + 2);
        float gv = __shfl_sync(0xffffffffu, val, base + 4);
        float ov = __shfl_sync(0xffffffffu, val, base + 6);

        if (prod) {
            cst = fmaf(fv, cst, iv * gv);
            float hv = ov * fast_tanh(cst);
            unsigned off = (unsigned)((s & 1) * HDIM + j) * 4u;
#pragma unroll
            for (int c = 0; c < CL; c++)            // broadcast slice to cluster
                asm volatile("st.shared::cluster.f32 [%0], %1;"
                             :: "r"(rh[c] + off), "f"(hv) : "memory");
            __stcg(&g_hs[d][t][j], hv);
        }
        __syncthreads();                            // all stores of this CTA issued
        if (tid == 0) {
            asm volatile("fence.acq_rel.cluster;" ::: "memory");
#pragma unroll
            for (int c = 0; c < CL; c++)
                asm volatile("mbarrier.arrive.shared::cluster.b64 _, [%0];"
                             :: "r"(rm[c]) : "memory");
        }
    }

    // no CTA may exit while peers still write into its SMEM
    asm volatile("barrier.cluster.arrive.aligned;" ::: "memory");
    asm volatile("barrier.cluster.wait.aligned;"   ::: "memory");
}

// ---------------- K3: feats[t] = [hs_f[t], hs_b[S-1-t]] @ lin_w^T + lin_b --------
__global__ void k3_feats(const float* __restrict__ lin_w, const float* __restrict__ lin_b)
{
    __shared__ __align__(16) float cat[2 * HDIM];
    const int t   = blockIdx.x;
    const int tid = threadIdx.x;                // 256
    cat[tid]        = g_hs[0][t][tid];
    cat[HDIM + tid] = g_hs[1][SLEN - 1 - t][tid];
    __syncthreads();

    const int n = tid >> 3, seg = tid & 7;
    const float* w  = lin_w + (size_t)n * 2 * HDIM + seg * 64;
    const float* cc = cat + seg * 64;
    float s = 0.0f;
#pragma unroll 16
    for (int k = 0; k < 64; k++) s = fmaf(w[k], cc[k], s);
    s += __shfl_xor_sync(0xffffffffu, s, 1);
    s += __shfl_xor_sync(0xffffffffu, s, 2);
    s += __shfl_xor_sync(0xffffffffu, s, 4);
    if (seg == 0) g_feats[t][n] = s + lin_b[n];
}

// ---------------- K4: single-warp Viterbi + backtrack (bps in SMEM) --------------
__global__ void __launch_bounds__(32, 1) k4_viterbi(
    const float* __restrict__ trans, float* __restrict__ out, int out_size)
{
    extern __shared__ unsigned char bps[];      // SLEN*TAGS bytes = 128 KB
    const int lane = threadIdx.x;

    float trn[TAGS];
#pragma unroll
    for (int p = 0; p < TAGS; p++) trn[p] = __ldg(&trans[lane * TAGS + p]);
    const float stop_tr = __ldg(&trans[STOPTAG * TAGS + lane]);

    float fv  = (lane == STARTTAG) ? 0.0f : NEGV;
    float ftc = g_feats[0][lane];
    float ftn = g_feats[1][lane];

    for (int t = 0; t < SLEN; t++) {
        float v[TAGS];
        int   bi[TAGS];
#pragma unroll
        for (int p = 0; p < TAGS; p++) {
            v[p]  = __shfl_sync(0xffffffffu, fv, p) + trn[p];
            bi[p] = p;
        }
        // first-max tree: strict > keeps the lower index on ties (== jnp.argmax)
#pragma unroll
        for (int s = 1; s < TAGS; s <<= 1) {
#pragma unroll
            for (int k = 0; k < TAGS; k += 2 * s) {
                if (v[k + s] > v[k]) { v[k] = v[k + s]; bi[k] = bi[k + s]; }
            }
        }
        bps[t * TAGS + lane] = (unsigned char)bi[0];
        fv  = v[0] + ftc;
        ftc = ftn;
        ftn = (t + 2 < SLEN) ? g_feats[t + 2][lane] : 0.0f;
    }

    float v = fv + stop_tr;
    int   b = lane;
#pragma unroll
    for (int ofs = 16; ofs > 0; ofs >>= 1) {
        float ov = __shfl_down_sync(0xffffffffu, v, ofs);
        int   oi = __shfl_down_sync(0xffffffffu, b, ofs);
        if (ov > v || (ov == v && oi < b)) { v = ov; b = oi; }
    }

    if (lane == 0) {
        const int off = (out_size > SLEN) ? 1 : 0;
        if (off) out[0] = v;
        int cur = b;
        for (int t = SLEN - 1; t >= 0; t--) {
            int idx = off + t;
            if (idx < out_size) out[idx] = (float)cur;
            cur = bps[t * TAGS + cur];
        }
    }
}

// ---------------- launch ----------------------------------------------------------
extern "C" void kernel_launch(void* const* d_in, const int* in_sizes, int n_in,
                              void* d_out, int out_size)
{
    (void)in_sizes; (void)n_in;
    const int*   sent      = (const int*)  d_in[0];
    const float* h0        = (const float*)d_in[1];
    const float* c0        = (const float*)d_in[2];
    const float* embedding = (const float*)d_in[3];
    const float* w_ih_f    = (const float*)d_in[4];
    const float* w_hh_f    = (const float*)d_in[5];
    const float* b_f       = (const float*)d_in[6];
    const float* w_ih_b    = (const float*)d_in[7];
    const float* w_hh_b    = (const float*)d_in[8];
    const float* b_b       = (const float*)d_in[9];
    const float* lin_w     = (const float*)d_in[10];
    const float* lin_b     = (const float*)d_in[11];
    const float* trans     = (const float*)d_in[12];

    dim3 g1(SLEN / 16, 4, 2);
    k1_xg<<<g1, 256>>>(sent, embedding, w_ih_f, b_f, w_ih_b, b_b);
    k2_lstm<<<2 * CL, 256>>>(h0, c0, w_hh_f, w_hh_b);
    k3_feats<<<SLEN, 256>>>(lin_w, lin_b);

    cudaFuncSetAttribute(k4_viterbi, cudaFuncAttributeMaxDynamicSharedMemorySize,
                         SLEN * TAGS);
    k4_viterbi<<<1, 32, SLEN * TAGS>>>(trans, (float*)d_out, out_size);
}